// round 9
// baseline (speedup 1.0000x reference)
#include <cuda_runtime.h>

#define RH 256
#define RW 256
#define NPIX (RH * RW)
#define NTILES 256          // 16x16 tiles of 16x16 px
#define NB 16               // dlo buckets, uniform on [1,2]
#define NMAX 4
#define FMAX 16384
#define CAP 1024            // per-(n,tile,bucket) list capacity
#define CAPSH 10
#define REPS 1e-8f
#define MARGIN 0.5f
#define TAILMAX 64

struct __align__(16) FSg {
    float x2, y2, A0, B0;
    float A1, B1, inv, z0;
    float z1, z2; int i0, i1;
    int i2; float zmin; unsigned bbox; float denom;
};  // bbox: xlo|xhi<<8|ylo<<16|yhi<<24 (pixel precision); xlo>xhi => invalid

static __device__ FSg g_fs[NMAX * FMAX];
static __device__ unsigned g_cnt[NMAX * NTILES * NB];
static __device__ int g_bnd[4];   // global coverage bounds: xlo, xhi, ylo, yhi
// entry = (dlo_bits << 32) | face_idx
static __device__ unsigned long long g_ent[(size_t)NMAX * NTILES * NB * CAP];

__global__ void k_clear(int nbins) {
    int i = blockIdx.x * blockDim.x + threadIdx.x;
    if (i < nbins) g_cnt[i] = 0u;
    if (i < 2) { g_bnd[i * 2] = 0x7fffffff; g_bnd[i * 2 + 1] = -1; }
}

// One thread per (n, face): reference-bitwise setup (__f*_rn, no fma).
__global__ void k_setup(const float* __restrict__ verts,
                        const int* __restrict__ faces,
                        int N, int V, int F) {
    int idx = blockIdx.x * blockDim.x + threadIdx.x;
    int lane = threadIdx.x & 31;
    int bxlo = 0x7fffffff, bxhi = -1, bylo = 0x7fffffff, byhi = -1;

    if (idx < N * F) {
        int n = idx / F, f = idx - n * F;
        FSg s;
        int i0 = faces[3 * f + 0];
        int i1 = faces[3 * f + 1];
        int i2 = faces[3 * f + 2];
        const float* base = verts + (size_t)n * (size_t)V * 3;
        float vx0 = base[3 * i0 + 0], vy0 = base[3 * i0 + 1], vz0 = base[3 * i0 + 2];
        float vx1 = base[3 * i1 + 0], vy1 = base[3 * i1 + 1], vz1 = base[3 * i1 + 2];
        float vx2 = base[3 * i2 + 0], vy2 = base[3 * i2 + 1], vz2 = base[3 * i2 + 2];
        float x0 = __fdiv_rn(vx0, vz0), y0 = __fdiv_rn(vy0, vz0);
        float x1 = __fdiv_rn(vx1, vz1), y1 = __fdiv_rn(vy1, vz1);
        float x2 = __fdiv_rn(vx2, vz2), y2 = __fdiv_rn(vy2, vz2);
        s.x2 = x2; s.y2 = y2;
        s.z0 = vz0; s.z1 = vz1; s.z2 = vz2;
        s.A0 = __fsub_rn(y1, y2);
        s.B0 = __fsub_rn(x2, x1);
        s.A1 = __fsub_rn(y2, y0);
        s.B1 = __fsub_rn(x0, x2);
        float denom = __fadd_rn(__fmul_rn(s.A0, __fsub_rn(x0, x2)),
                                __fmul_rn(s.B0, __fsub_rn(y0, y2)));
        bool nz = fabsf(denom) > REPS;
        bool valid = nz && (vz0 > 0.0f) && (vz1 > 0.0f) && (vz2 > 0.0f);
        s.inv = __fdiv_rn(1.0f, nz ? denom : 1.0f);
        s.denom = nz ? denom : 1.0f;
        s.i0 = i0; s.i1 = i1; s.i2 = i2;
        s.zmin = fminf(vz0, fminf(vz1, vz2));

        float minx = fminf(x0, fminf(x1, x2));
        float maxx = fmaxf(x0, fmaxf(x1, x2));
        float miny = fminf(y0, fminf(y1, y2));
        float maxy = fmaxf(y0, fmaxf(y1, y2));
        int xlo = max(0, (int)ceilf(minx - MARGIN));
        int xhi = min(RW - 1, (int)floorf(maxx + MARGIN));
        int ylo = max(0, (int)ceilf(miny - MARGIN));
        int yhi = min(RH - 1, (int)floorf(maxy + MARGIN));
        if (xlo > xhi || ylo > yhi) valid = false;

        s.bbox = valid ? ((unsigned)xlo | ((unsigned)xhi << 8) |
                          ((unsigned)ylo << 16) | ((unsigned)yhi << 24))
                       : 0x000000FFu;   // xlo=255 > xhi=0 -> invalid
        g_fs[idx] = s;
        if (valid) { bxlo = xlo; bxhi = xhi; bylo = ylo; byhi = yhi; }
    }

#pragma unroll
    for (int o = 16; o; o >>= 1) {
        bxlo = min(bxlo, __shfl_xor_sync(0xffffffffu, bxlo, o));
        bxhi = max(bxhi, __shfl_xor_sync(0xffffffffu, bxhi, o));
        bylo = min(bylo, __shfl_xor_sync(0xffffffffu, bylo, o));
        byhi = max(byhi, __shfl_xor_sync(0xffffffffu, byhi, o));
    }
    if (lane == 0 && bxhi >= 0) {
        atomicMin(&g_bnd[0], bxlo);
        atomicMax(&g_bnd[1], bxhi);
        atomicMin(&g_bnd[2], bylo);
        atomicMax(&g_bnd[3], byhi);
    }
}

// One warp per (n, face): exact tri-vs-tile overlap test, per-tile affine
// depth lower bound, bucket by dlo, append entry.
__global__ void k_bin(int N, int F) {
    int gw = (blockIdx.x * blockDim.x + threadIdx.x) >> 5;
    int lane = threadIdx.x & 31;
    if (gw >= N * F) return;
    int n = gw / F, f = gw - n * F;

    FSg s = g_fs[gw];   // broadcast load
    unsigned bbx = s.bbox;
    int xlo = bbx & 255, xhi = (bbx >> 8) & 255;
    int ylo = (bbx >> 16) & 255, yhi = (bbx >> 24) & 255;
    if (xlo > xhi) return;

    float sgn = (s.inv < 0.0f) ? -1.0f : 1.0f;
    float a0 = s.A0 * sgn, b0 = s.B0 * sgn;
    float a1 = s.A1 * sgn, b1 = s.B1 * sgn;
    float a2 = -(s.A0 + s.A1) * sgn, b2 = -(s.B0 + s.B1) * sgn;
    float c2 = s.denom * sgn;
    float tol0 = 1.0f + 1e-4f * (fabsf(a0) + fabsf(b0)) * 256.0f;
    float tol1 = 1.0f + 1e-4f * (fabsf(a1) + fabsf(b1)) * 256.0f;
    float tol2 = 1.0f + 1e-4f * ((fabsf(a2) + fabsf(b2)) * 256.0f + fabsf(c2));

    float dz0 = s.z0 - s.z2, dz1 = s.z1 - s.z2;
    float Gx = (s.A0 * dz0 + s.A1 * dz1) * s.inv;
    float Gy = (s.B0 * dz0 + s.B1 * dz1) * s.inv;
    float slack = 5e-7f * (260.0f * fabsf(s.inv) *
                           ((fabsf(s.A0) + fabsf(s.B0)) * fabsf(dz0) +
                            (fabsf(s.A1) + fabsf(s.B1)) * fabsf(dz1)) +
                           1040.0f * (fabsf(Gx) + fabsf(Gy))) + 2e-5f;
    float zlb = s.zmin - 1e-5f;

    int txlo = xlo >> 4, txhi = xhi >> 4, tylo = ylo >> 4, tyhi = yhi >> 4;
    int w = txhi - txlo + 1, h = tyhi - tylo + 1, cnt = w * h;

    for (int t = lane; t < cnt; t += 32) {
        int tx = txlo + t % w, ty = tylo + t / w;
        float dxmin = (float)(tx << 4) - s.x2, dxmax = dxmin + 15.0f;
        float dymin = (float)(ty << 4) - s.y2, dymax = dymin + 15.0f;
        float v0 = fmaxf(a0 * dxmin, a0 * dxmax) + fmaxf(b0 * dymin, b0 * dymax);
        float v1 = fmaxf(a1 * dxmin, a1 * dxmax) + fmaxf(b1 * dymin, b1 * dymax);
        float v2 = fmaxf(a2 * dxmin, a2 * dxmax) + fmaxf(b2 * dymin, b2 * dymax) + c2;
        if (v0 >= -tol0 && v1 >= -tol1 && v2 >= -tol2) {
            float affmin = s.z2 + fminf(Gx * dxmin, Gx * dxmax) +
                                  fminf(Gy * dymin, Gy * dymax);
            float dlo = fmaxf(fmaxf(affmin - slack, zlb), 0.0f);
            int bkt = (int)floorf((dlo - 1.0f) * 16.0f);
            bkt = max(0, min(NB - 1, bkt));
            int bin = (n << 12) | (((ty << 4) | tx) << 4) | bkt;
            unsigned slot = atomicAdd(&g_cnt[bin], 1u);
            if (slot < CAP)
                g_ent[((size_t)bin << CAPSH) + slot] =
                    (((unsigned long long)__float_as_uint(dlo)) << 32) |
                    (unsigned int)f;
        }
    }
}

// One block per (n, tile, half): 128 threads, 16x8 px. Register z-key min,
// ascending-dlo buckets with exact break. NEW: done pixels never scan;
// bbox fast-reject before eval; when <=TAILMAX pixels remain unresolved the
// block switches to entry-parallel "tail mode" (smem atomicMin on keys) so
// a few stuck border pixels don't serialize a whole block.
__global__ void __launch_bounds__(128) k_tile(const float* __restrict__ colors,
                                              float* __restrict__ out,
                                              int N, int V, int F) {
    __shared__ FSg sm[128];
    __shared__ unsigned long long sk[128];
    __shared__ unsigned sbb[128];
    __shared__ unsigned long long s_key[TAILMAX];
    __shared__ unsigned s_px[TAILMAX];
    __shared__ int s_nt;
    __shared__ int s_myslot[128];

    int blk = blockIdx.x;
    int n = blk >> 9;
    int r = blk & 511;
    int tile = r >> 1, half = r & 1;
    int tid = threadIdx.x;
    int x = ((tile & 15) << 4) + (tid & 15);
    int y = ((tile >> 4) << 4) + (half << 3) + (tid >> 4);
    float xf = (float)x, yf = (float)y;
    unsigned long long cur = ~0ULL;
    bool done = (x < g_bnd[0]) | (x > g_bnd[1]) | (y < g_bnd[2]) | (y > g_bnd[3]);
    bool tail = false;

    for (int b = 0; b < NB; ++b) {
        float lbf = 1.0f + (float)b * 0.0625f;
        unsigned long long lb = (b == 0) ? 0ULL :
            (((unsigned long long)__float_as_uint(lbf)) << 32);

        if (!tail) {
            bool unres = !done && cur > lb;
            int cnt = __syncthreads_count(unres);
            if (cnt == 0) break;
            if (cnt <= TAILMAX) {
                tail = true;
                if (tid == 0) s_nt = 0;
                s_myslot[tid] = -1;
                __syncthreads();
                if (unres) {
                    int slot = atomicAdd(&s_nt, 1);
                    s_myslot[tid] = slot;
                    s_key[slot] = cur;
                    s_px[slot] = (unsigned)x | ((unsigned)y << 8);
                }
                __syncthreads();
            }
        } else {
            bool p = (tid < s_nt) && (s_key[tid] > lb);
            if (!__syncthreads_or(p)) break;
        }

        int bin = (n << 12) | (tile << 4) | b;
        unsigned total = min(g_cnt[bin], (unsigned)CAP);

        if (tail) {
            // entry-parallel: one entry per thread, tested vs all stuck px
            int nt = s_nt;
            for (unsigned e = tid; e < total; e += 128) {
                unsigned long long ek = g_ent[((size_t)bin << CAPSH) + e];
                const uint4* src =
                    (const uint4*)&g_fs[n * F + (int)(unsigned)(ek & 0xffffffffULL)];
                uint4 d3 = src[3];
                unsigned bb = d3.z;
                uint4 d0, d1, d2;
                bool loaded = false;
                for (int i = 0; i < nt; ++i) {
                    unsigned long long k = s_key[i];
                    if (k <= ek) continue;
                    unsigned px = s_px[i];
                    int xi = px & 255, yi = (px >> 8) & 255;
                    int t = (xi - (int)(bb & 255u)) | ((int)((bb >> 8) & 255u) - xi) |
                            (yi - (int)((bb >> 16) & 255u)) | ((int)(bb >> 24) - yi);
                    if (t < 0) continue;
                    if (!loaded) { d0 = src[0]; d1 = src[1]; d2 = src[2]; loaded = true; }
                    float dx = __fsub_rn((float)xi, __uint_as_float(d0.x));
                    float dy = __fsub_rn((float)yi, __uint_as_float(d0.y));
                    float inv = __uint_as_float(d1.z);
                    float w0 = __fmul_rn(__fadd_rn(
                        __fmul_rn(__uint_as_float(d0.z), dx),
                        __fmul_rn(__uint_as_float(d0.w), dy)), inv);
                    float w1 = __fmul_rn(__fadd_rn(
                        __fmul_rn(__uint_as_float(d1.x), dx),
                        __fmul_rn(__uint_as_float(d1.y), dy)), inv);
                    float w2 = __fsub_rn(__fsub_rn(1.0f, w0), w1);
                    if (fminf(fminf(w0, w1), w2) >= 0.0f) {
                        float depth = __fadd_rn(__fadd_rn(
                            __fmul_rn(w0, __uint_as_float(d1.w)),
                            __fmul_rn(w1, __uint_as_float(d2.x))),
                            __fmul_rn(w2, __uint_as_float(d2.y)));
                        if (depth > 0.0f) {
                            unsigned long long key =
                                (((unsigned long long)__float_as_uint(depth)) << 32) |
                                (ek & 0xffffffffULL);
                            if (key < k) atomicMin(&s_key[i], key);
                        }
                    }
                }
            }
        } else {
            for (unsigned c = 0; c < total; c += 128) {
                unsigned m = min(128u, total - c);
                __syncthreads();
                if ((unsigned)tid < m) {
                    unsigned long long e = g_ent[((size_t)bin << CAPSH) + c + tid];
                    sk[tid] = e;
                    const uint4* src =
                        (const uint4*)&g_fs[n * F + (int)(unsigned)(e & 0xffffffffULL)];
                    uint4 d0 = src[0], d1 = src[1], d2 = src[2], d3 = src[3];
                    uint4* dst = (uint4*)&sm[tid];
                    dst[0] = d0; dst[1] = d1; dst[2] = d2; dst[3] = d3;
                    sbb[tid] = d3.z;
                }
                __syncthreads();
                if (!done) {
#pragma unroll 4
                    for (unsigned j = 0; j < m; ++j) {
                        unsigned long long ek = sk[j];
                        if (cur <= ek) continue;
                        unsigned bb = sbb[j];
                        int t = (x - (int)(bb & 255u)) | ((int)((bb >> 8) & 255u) - x) |
                                (y - (int)((bb >> 16) & 255u)) | ((int)(bb >> 24) - y);
                        if (t < 0) continue;
                        float dx = __fsub_rn(xf, sm[j].x2);
                        float dy = __fsub_rn(yf, sm[j].y2);
                        float w0 = __fmul_rn(
                            __fadd_rn(__fmul_rn(sm[j].A0, dx), __fmul_rn(sm[j].B0, dy)),
                            sm[j].inv);
                        float w1 = __fmul_rn(
                            __fadd_rn(__fmul_rn(sm[j].A1, dx), __fmul_rn(sm[j].B1, dy)),
                            sm[j].inv);
                        float w2 = __fsub_rn(__fsub_rn(1.0f, w0), w1);
                        if (fminf(fminf(w0, w1), w2) >= 0.0f) {
                            float depth = __fadd_rn(
                                __fadd_rn(__fmul_rn(w0, sm[j].z0),
                                          __fmul_rn(w1, sm[j].z1)),
                                __fmul_rn(w2, sm[j].z2));
                            if (depth > 0.0f) {
                                unsigned long long key =
                                    (((unsigned long long)__float_as_uint(depth)) << 32) |
                                    (ek & 0xffffffffULL);
                                if (key < cur) cur = key;
                            }
                        }
                    }
                }
            }
        }
    }
    __syncthreads();
    if (tail && s_myslot[tid] >= 0) cur = s_key[s_myslot[tid]];

    // resolve inline
    int pix = (y << 8) | x;
    float res[8];
#pragma unroll
    for (int ch = 0; ch < 8; ++ch) res[ch] = 0.0f;
    bool anypos = false;
    if (cur != ~0ULL) {
        int f = (int)(unsigned)(cur & 0xffffffffULL);
        FSg s = g_fs[n * F + f];
        float dx = __fsub_rn(xf, s.x2);
        float dy = __fsub_rn(yf, s.y2);
        float w0 = __fmul_rn(
            __fadd_rn(__fmul_rn(s.A0, dx), __fmul_rn(s.B0, dy)), s.inv);
        float w1 = __fmul_rn(
            __fadd_rn(__fmul_rn(s.A1, dx), __fmul_rn(s.B1, dy)), s.inv);
        float w2 = __fsub_rn(__fsub_rn(1.0f, w0), w1);
        const float* cb = colors + (size_t)n * (size_t)V * 8;
        const float* c0 = cb + (size_t)s.i0 * 8;
        const float* c1 = cb + (size_t)s.i1 * 8;
        const float* c2 = cb + (size_t)s.i2 * 8;
#pragma unroll
        for (int ch = 0; ch < 8; ++ch) {
            float c = __fadd_rn(
                __fadd_rn(__fmul_rn(w0, c0[ch]), __fmul_rn(w1, c1[ch])),
                __fmul_rn(w2, c2[ch]));
            res[ch] = c;
            anypos = anypos || (c > 0.0f);
        }
    }
#pragma unroll
    for (int ch = 0; ch < 8; ++ch) {
        float v = anypos ? res[ch] : 0.0f;
        out[(((size_t)n * 8 + ch) << 16) + pix] = v;
    }
}

extern "C" void kernel_launch(void* const* d_in, const int* in_sizes, int n_in,
                              void* d_out, int out_size) {
    const float* verts = (const float*)d_in[0];
    const float* colors = (const float*)d_in[1];
    const int* faces = (const int*)d_in[2];
    float* out = (float*)d_out;

    int F = in_sizes[2] / 3;
    int N = out_size / (8 * NPIX);
    if (N < 1) N = 1;
    if (N > NMAX) N = NMAX;
    int V = (in_sizes[0] / 3) / N;

    int nbins = N * NTILES * NB;
    k_clear<<<(nbins + 255) / 256, 256>>>(nbins);

    int nf = N * F;
    k_setup<<<(nf + 127) / 128, 128>>>(verts, faces, N, V, F);

    int bthreads = nf * 32;
    k_bin<<<(bthreads + 127) / 128, 128>>>(N, F);

    k_tile<<<N * NTILES * 2, 128>>>(colors, out, N, V, F);
}

// round 10
// speedup vs baseline: 1.6011x; 1.6011x over previous
#include <cuda_runtime.h>

#define RH 256
#define RW 256
#define NPIX (RH * RW)
#define NTILES 256          // 16x16 tiles of 16x16 px
#define NB 16               // dlo buckets, uniform on [1,2]
#define NMAX 4
#define FMAX 16384
#define CAP 1024            // per-(n,tile,bucket) list capacity
#define CAPSH 10
#define REPS 1e-8f
#define MARGIN 0.5f

struct __align__(16) FSg {
    float x2, y2, A0, B0;
    float A1, B1, inv, z0;
    float z1, z2; int i0, i1;
    int i2; float zmin; unsigned meta; float denom;
};

static __device__ FSg g_fs[NMAX * FMAX];
static __device__ unsigned g_cnt[NMAX * NTILES * NB];
static __device__ int g_bnd[4];   // global coverage bounds: xlo, xhi, ylo, yhi
// entry = (dlo_bits << 32) | face_idx ; dlo = lower bound of this face's
// reference-computed depth at any accepted pixel of this tile.
static __device__ unsigned long long g_ent[(size_t)NMAX * NTILES * NB * CAP];

__global__ void k_clear(int nbins) {
    int i = blockIdx.x * blockDim.x + threadIdx.x;
    if (i < nbins) g_cnt[i] = 0u;
    if (i < 2) { g_bnd[i * 2] = 0x7fffffff; g_bnd[i * 2 + 1] = -1; }
}

// One thread per (n, face): reference-bitwise setup (__f*_rn, no fma).
__global__ void k_setup(const float* __restrict__ verts,
                        const int* __restrict__ faces,
                        int N, int V, int F) {
    int idx = blockIdx.x * blockDim.x + threadIdx.x;
    int lane = threadIdx.x & 31;
    int bxlo = 0x7fffffff, bxhi = -1, bylo = 0x7fffffff, byhi = -1;

    if (idx < N * F) {
        int n = idx / F, f = idx - n * F;
        FSg s;
        int i0 = faces[3 * f + 0];
        int i1 = faces[3 * f + 1];
        int i2 = faces[3 * f + 2];
        const float* base = verts + (size_t)n * (size_t)V * 3;
        float vx0 = base[3 * i0 + 0], vy0 = base[3 * i0 + 1], vz0 = base[3 * i0 + 2];
        float vx1 = base[3 * i1 + 0], vy1 = base[3 * i1 + 1], vz1 = base[3 * i1 + 2];
        float vx2 = base[3 * i2 + 0], vy2 = base[3 * i2 + 1], vz2 = base[3 * i2 + 2];
        float x0 = __fdiv_rn(vx0, vz0), y0 = __fdiv_rn(vy0, vz0);
        float x1 = __fdiv_rn(vx1, vz1), y1 = __fdiv_rn(vy1, vz1);
        float x2 = __fdiv_rn(vx2, vz2), y2 = __fdiv_rn(vy2, vz2);
        s.x2 = x2; s.y2 = y2;
        s.z0 = vz0; s.z1 = vz1; s.z2 = vz2;
        s.A0 = __fsub_rn(y1, y2);
        s.B0 = __fsub_rn(x2, x1);
        s.A1 = __fsub_rn(y2, y0);
        s.B1 = __fsub_rn(x0, x2);
        float denom = __fadd_rn(__fmul_rn(s.A0, __fsub_rn(x0, x2)),
                                __fmul_rn(s.B0, __fsub_rn(y0, y2)));
        bool nz = fabsf(denom) > REPS;
        bool valid = nz && (vz0 > 0.0f) && (vz1 > 0.0f) && (vz2 > 0.0f);
        s.inv = __fdiv_rn(1.0f, nz ? denom : 1.0f);
        s.denom = nz ? denom : 1.0f;
        s.i0 = i0; s.i1 = i1; s.i2 = i2;
        s.zmin = fminf(vz0, fminf(vz1, vz2));

        float minx = fminf(x0, fminf(x1, x2));
        float maxx = fmaxf(x0, fmaxf(x1, x2));
        float miny = fminf(y0, fminf(y1, y2));
        float maxy = fmaxf(y0, fmaxf(y1, y2));
        int xlo = max(0, (int)ceilf(minx - MARGIN));
        int xhi = min(RW - 1, (int)floorf(maxx + MARGIN));
        int ylo = max(0, (int)ceilf(miny - MARGIN));
        int yhi = min(RH - 1, (int)floorf(maxy + MARGIN));
        if (xlo > xhi || ylo > yhi) valid = false;

        s.meta = valid ? ((unsigned)(xlo >> 4) | ((unsigned)(xhi >> 4) << 4) |
                          ((unsigned)(ylo >> 4) << 8) | ((unsigned)(yhi >> 4) << 12) |
                          (1u << 16))
                       : 0u;
        g_fs[idx] = s;
        if (valid) { bxlo = xlo; bxhi = xhi; bylo = ylo; byhi = yhi; }
    }

#pragma unroll
    for (int o = 16; o; o >>= 1) {
        bxlo = min(bxlo, __shfl_xor_sync(0xffffffffu, bxlo, o));
        bxhi = max(bxhi, __shfl_xor_sync(0xffffffffu, bxhi, o));
        bylo = min(bylo, __shfl_xor_sync(0xffffffffu, bylo, o));
        byhi = max(byhi, __shfl_xor_sync(0xffffffffu, byhi, o));
    }
    if (lane == 0 && bxhi >= 0) {
        atomicMin(&g_bnd[0], bxlo);
        atomicMax(&g_bnd[1], bxhi);
        atomicMin(&g_bnd[2], bylo);
        atomicMax(&g_bnd[3], byhi);
    }
}

// One warp per (n, face): exact tri-vs-tile overlap test, per-tile affine
// depth lower bound, bucket by dlo, append entry.
__global__ void k_bin(int N, int F) {
    int gw = (blockIdx.x * blockDim.x + threadIdx.x) >> 5;
    int lane = threadIdx.x & 31;
    if (gw >= N * F) return;
    int n = gw / F, f = gw - n * F;

    FSg s = g_fs[gw];   // broadcast load (all lanes same address)
    unsigned m = s.meta;
    if (!(m & (1u << 16))) return;

    // sign-normalized half planes for the tile overlap test
    float sgn = (s.inv < 0.0f) ? -1.0f : 1.0f;
    float a0 = s.A0 * sgn, b0 = s.B0 * sgn;
    float a1 = s.A1 * sgn, b1 = s.B1 * sgn;
    float a2 = -(s.A0 + s.A1) * sgn, b2 = -(s.B0 + s.B1) * sgn;
    float c2 = s.denom * sgn;
    float tol0 = 1.0f + 1e-4f * (fabsf(a0) + fabsf(b0)) * 256.0f;
    float tol1 = 1.0f + 1e-4f * (fabsf(a1) + fabsf(b1)) * 256.0f;
    float tol2 = 1.0f + 1e-4f * ((fabsf(a2) + fabsf(b2)) * 256.0f + fabsf(c2));

    // affine depth: d(x,y) = z2 + Gx*dx + Gy*dy
    float dz0 = s.z0 - s.z2, dz1 = s.z1 - s.z2;
    float Gx = (s.A0 * dz0 + s.A1 * dz1) * s.inv;
    float Gy = (s.B0 * dz0 + s.B1 * dz1) * s.inv;
    // rigorous rounding slack for the affine bound; blows up for slivers,
    // where the always-valid (zmin - eps) bound below takes over.
    float slack = 5e-7f * (260.0f * fabsf(s.inv) *
                           ((fabsf(s.A0) + fabsf(s.B0)) * fabsf(dz0) +
                            (fabsf(s.A1) + fabsf(s.B1)) * fabsf(dz1)) +
                           1040.0f * (fabsf(Gx) + fabsf(Gy))) + 2e-5f;
    float zlb = s.zmin - 1e-5f;

    int txlo = m & 15, txhi = (m >> 4) & 15;
    int tylo = (m >> 8) & 15, tyhi = (m >> 12) & 15;
    int w = txhi - txlo + 1, h = tyhi - tylo + 1, cnt = w * h;

    for (int t = lane; t < cnt; t += 32) {
        int tx = txlo + t % w, ty = tylo + t / w;
        float dxmin = (float)(tx << 4) - s.x2, dxmax = dxmin + 15.0f;
        float dymin = (float)(ty << 4) - s.y2, dymax = dymin + 15.0f;
        float v0 = fmaxf(a0 * dxmin, a0 * dxmax) + fmaxf(b0 * dymin, b0 * dymax);
        float v1 = fmaxf(a1 * dxmin, a1 * dxmax) + fmaxf(b1 * dymin, b1 * dymax);
        float v2 = fmaxf(a2 * dxmin, a2 * dxmax) + fmaxf(b2 * dymin, b2 * dymax) + c2;
        if (v0 >= -tol0 && v1 >= -tol1 && v2 >= -tol2) {
            float affmin = s.z2 + fminf(Gx * dxmin, Gx * dxmax) +
                                  fminf(Gy * dymin, Gy * dymax);
            float dlo = fmaxf(fmaxf(affmin - slack, zlb), 0.0f);
            int bkt = (int)floorf((dlo - 1.0f) * 16.0f);
            bkt = max(0, min(NB - 1, bkt));
            int bin = (n << 12) | (((ty << 4) | tx) << 4) | bkt;
            unsigned slot = atomicAdd(&g_cnt[bin], 1u);
            if (slot < CAP)
                g_ent[((size_t)bin << CAPSH) + slot] =
                    (((unsigned long long)__float_as_uint(dlo)) << 32) |
                    (unsigned int)f;
        }
    }
}

// One block per (n, tile, half-tile): 128 threads, one 16x8 pixel half-tile.
// Register z-key (depth_bits<<32 | face) min reproduces the reference
// tie-break exactly. Buckets scanned in ascending dlo order; break when all
// pixels are done (provably uncoverable: outside global coverage bounds) or
// satisfied (cur <= bucket lower bound). Done pixels skip the scan loop
// entirely — previously they full-evaluated every entry at cur=~0, making
// the ~120 border-band blocks the kernel's critical path.
__global__ void __launch_bounds__(128) k_tile(const float* __restrict__ colors,
                                              float* __restrict__ out,
                                              int N, int V, int F) {
    __shared__ FSg sm[128];
    __shared__ unsigned long long sk[128];
    int blk = blockIdx.x;
    int n = blk >> 9;
    int r = blk & 511;
    int tile = r >> 1, half = r & 1;
    int tid = threadIdx.x;
    int x = ((tile & 15) << 4) + (tid & 15);
    int y = ((tile >> 4) << 4) + (half << 3) + (tid >> 4);
    float xf = (float)x, yf = (float)y;
    unsigned long long cur = ~0ULL;

    bool done = (x < g_bnd[0]) | (x > g_bnd[1]) | (y < g_bnd[2]) | (y > g_bnd[3]);

    for (int b = 0; b < NB; ++b) {
        if (b > 0) {
            float lbf = 1.0f + (float)b * 0.0625f;
            unsigned long long lb =
                ((unsigned long long)__float_as_uint(lbf)) << 32;
            if (__syncthreads_and(done || cur <= lb)) break;
        }
        int bin = (n << 12) | (tile << 4) | b;
        unsigned total = min(g_cnt[bin], (unsigned)CAP);
        for (unsigned c = 0; c < total; c += 128) {
            unsigned m = min(128u, total - c);
            __syncthreads();
            if ((unsigned)tid < m) {
                unsigned long long e = g_ent[((size_t)bin << CAPSH) + c + tid];
                sk[tid] = e;
                const uint4* src =
                    (const uint4*)&g_fs[n * F + (int)(unsigned)(e & 0xffffffffULL)];
                uint4* dst = (uint4*)&sm[tid];
                dst[0] = src[0]; dst[1] = src[1]; dst[2] = src[2]; dst[3] = src[3];
            }
            __syncthreads();
            if (!done) {
#pragma unroll 4
                for (unsigned j = 0; j < m; ++j) {
                    unsigned long long ek = sk[j];
                    if (cur <= ek) continue;
                    float dx = __fsub_rn(xf, sm[j].x2);
                    float dy = __fsub_rn(yf, sm[j].y2);
                    float w0 = __fmul_rn(
                        __fadd_rn(__fmul_rn(sm[j].A0, dx), __fmul_rn(sm[j].B0, dy)),
                        sm[j].inv);
                    float w1 = __fmul_rn(
                        __fadd_rn(__fmul_rn(sm[j].A1, dx), __fmul_rn(sm[j].B1, dy)),
                        sm[j].inv);
                    float w2 = __fsub_rn(__fsub_rn(1.0f, w0), w1);
                    if (fminf(fminf(w0, w1), w2) >= 0.0f) {
                        float depth = __fadd_rn(
                            __fadd_rn(__fmul_rn(w0, sm[j].z0),
                                      __fmul_rn(w1, sm[j].z1)),
                            __fmul_rn(w2, sm[j].z2));
                        if (depth > 0.0f) {
                            unsigned long long key =
                                (((unsigned long long)__float_as_uint(depth)) << 32) |
                                (ek & 0xffffffffULL);
                            if (key < cur) cur = key;
                        }
                    }
                }
            }
        }
    }

    // resolve inline
    int pix = (y << 8) | x;
    float res[8];
#pragma unroll
    for (int ch = 0; ch < 8; ++ch) res[ch] = 0.0f;
    bool anypos = false;
    if (cur != ~0ULL) {
        int f = (int)(unsigned)(cur & 0xffffffffULL);
        FSg s = g_fs[n * F + f];
        float dx = __fsub_rn(xf, s.x2);
        float dy = __fsub_rn(yf, s.y2);
        float w0 = __fmul_rn(
            __fadd_rn(__fmul_rn(s.A0, dx), __fmul_rn(s.B0, dy)), s.inv);
        float w1 = __fmul_rn(
            __fadd_rn(__fmul_rn(s.A1, dx), __fmul_rn(s.B1, dy)), s.inv);
        float w2 = __fsub_rn(__fsub_rn(1.0f, w0), w1);
        const float* cb = colors + (size_t)n * (size_t)V * 8;
        const float* c0 = cb + (size_t)s.i0 * 8;
        const float* c1 = cb + (size_t)s.i1 * 8;
        const float* c2 = cb + (size_t)s.i2 * 8;
#pragma unroll
        for (int ch = 0; ch < 8; ++ch) {
            float c = __fadd_rn(
                __fadd_rn(__fmul_rn(w0, c0[ch]), __fmul_rn(w1, c1[ch])),
                __fmul_rn(w2, c2[ch]));
            res[ch] = c;
            anypos = anypos || (c > 0.0f);
        }
    }
#pragma unroll
    for (int ch = 0; ch < 8; ++ch) {
        float v = anypos ? res[ch] : 0.0f;
        out[(((size_t)n * 8 + ch) << 16) + pix] = v;
    }
}

extern "C" void kernel_launch(void* const* d_in, const int* in_sizes, int n_in,
                              void* d_out, int out_size) {
    const float* verts = (const float*)d_in[0];
    const float* colors = (const float*)d_in[1];
    const int* faces = (const int*)d_in[2];
    float* out = (float*)d_out;

    int F = in_sizes[2] / 3;
    int N = out_size / (8 * NPIX);
    if (N < 1) N = 1;
    if (N > NMAX) N = NMAX;
    int V = (in_sizes[0] / 3) / N;

    int nbins = N * NTILES * NB;
    k_clear<<<(nbins + 255) / 256, 256>>>(nbins);

    int nf = N * F;
    k_setup<<<(nf + 127) / 128, 128>>>(verts, faces, N, V, F);

    int bthreads = nf * 32;
    k_bin<<<(bthreads + 127) / 128, 128>>>(N, F);

    k_tile<<<N * NTILES * 2, 128>>>(colors, out, N, V, F);
}